// round 2
// baseline (speedup 1.0000x reference)
#include <cuda_runtime.h>
#include <math.h>

// FNO spectral conv, truncated separable DFTs with packed f32x2 FMA.
// B=8, H=W=256, CIN=COUT=32, M1=M2=16.
typedef unsigned long long u64;

// Scratch (device globals, SoA re/im).
__device__ __align__(16) float g_Tre[8 * 16 * 256 * 32];   // [b][kx][h][c]   4 MB
__device__ __align__(16) float g_Tim[8 * 16 * 256 * 32];
__device__ __align__(16) float g_Xre[32 * 16 * 8 * 32];    // [p*16+kx][b][c]
__device__ __align__(16) float g_Xim[32 * 16 * 8 * 32];
__device__ __align__(16) float g_Yre[8 * 32 * 32 * 16];    // [b][co][p][kx]
__device__ __align__(16) float g_Yim[8 * 32 * 32 * 16];
__device__ __align__(16) float g_Gre[8 * 256 * 16 * 32];   // [b][h][kx][co]  4 MB
__device__ __align__(16) float g_Gim[8 * 256 * 16 * 32];

__device__ __forceinline__ u64 pack2(float lo, float hi) {
    u64 r; asm("mov.b64 %0,{%1,%2};" : "=l"(r) : "f"(lo), "f"(hi)); return r;
}
__device__ __forceinline__ float2 unpack2(u64 v) {
    float2 f; asm("mov.b64 {%0,%1},%2;" : "=f"(f.x), "=f"(f.y) : "l"(v)); return f;
}
__device__ __forceinline__ u64 ffma2(u64 a, u64 b, u64 c) {
    u64 d; asm("fma.rn.f32x2 %0,%1,%2,%3;" : "=l"(d) : "l"(a), "l"(b), "l"(c)); return d;
}
__device__ __forceinline__ u64 fmul2(u64 a, u64 b) {
    u64 d; asm("mul.rn.f32x2 %0,%1,%2;" : "=l"(d) : "l"(a), "l"(b)); return d;
}

// ---------------------------------------------------------------------------
// K1: forward DFT over w.  T[b,kx,h,c] = sum_w x[b,h,w,c] * e^{-2pi i kx w/256}
// grid 2048 (b*256+h), 64 threads. Thread: 4 kx, channel pair (packed f32x2).
// ---------------------------------------------------------------------------
__global__ __launch_bounds__(64) void k1_dft_w(const float* __restrict__ x) {
    __shared__ __align__(16) float sx[8192];        // [w][c] 32 KB
    __shared__ __align__(16) float4 tab4[256];      // (c, c, -s, -s)
    const int t = threadIdx.x;
    const int blk = blockIdx.x;                     // b*256 + h

    for (int i = t; i < 256; i += 64) {
        float s, c; sincospif((float)i * (1.0f / 128.0f), &s, &c);
        tab4[i] = make_float4(c, c, -s, -s);
    }
    {
        const float4* xp = (const float4*)(x + (size_t)blk * 8192);
        float4* sxp = (float4*)sx;
        for (int i = t; i < 2048; i += 64) sxp[i] = xp[i];
    }
    __syncthreads();

    const int kx0 = (t >> 4) * 4;    // 0,4,8,12
    const int c0  = (t & 15) * 2;

    u64 aR0 = 0, aI0 = 0, aR1 = 0, aI1 = 0, aR2 = 0, aI2 = 0, aR3 = 0, aI3 = 0;
    int m0 = 0, m1 = 0, m2 = 0, m3 = 0;
#pragma unroll 2
    for (int w = 0; w < 256; w++) {
        const u64 xv = *(const u64*)&sx[w * 32 + c0];
        const ulonglong2 t0 = *(const ulonglong2*)&tab4[m0]; m0 = (m0 + kx0)     & 255;
        const ulonglong2 t1 = *(const ulonglong2*)&tab4[m1]; m1 = (m1 + kx0 + 1) & 255;
        const ulonglong2 t2 = *(const ulonglong2*)&tab4[m2]; m2 = (m2 + kx0 + 2) & 255;
        const ulonglong2 t3 = *(const ulonglong2*)&tab4[m3]; m3 = (m3 + kx0 + 3) & 255;
        aR0 = ffma2(xv, t0.x, aR0); aI0 = ffma2(xv, t0.y, aI0);
        aR1 = ffma2(xv, t1.x, aR1); aI1 = ffma2(xv, t1.y, aI1);
        aR2 = ffma2(xv, t2.x, aR2); aI2 = ffma2(xv, t2.y, aI2);
        aR3 = ffma2(xv, t3.x, aR3); aI3 = ffma2(xv, t3.y, aI3);
    }

    const int b = blk >> 8, h = blk & 255;
    u64 re[4] = {aR0, aR1, aR2, aR3}, im[4] = {aI0, aI1, aI2, aI3};
#pragma unroll
    for (int j = 0; j < 4; j++) {
        const int kx = kx0 + j;
        const size_t idx = ((size_t)((b * 16 + kx) * 256 + h)) * 32 + c0;
        *(float2*)&g_Tre[idx] = unpack2(re[j]);
        *(float2*)&g_Tim[idx] = unpack2(im[j]);
    }
}

// ---------------------------------------------------------------------------
// K2: forward DFT over h for 32 kept ky modes, f32x2 over channel pairs.
// grid (16 kx, 2 cHalf, 8 b), 128 threads: p = t>>3 (16 freqs), cpair = t&7.
// ---------------------------------------------------------------------------
__global__ __launch_bounds__(128) void k2_dft_h() {
    __shared__ __align__(16) float sTre[4096], sTim[4096];  // [h][cl]
    __shared__ __align__(16) float4 tab4[256];              // (c, c, s, s)
    const int t = threadIdx.x;
    const int kx = blockIdx.x, ch = blockIdx.y, b = blockIdx.z;

    for (int i = t; i < 256; i += 128) {
        float s, c; sincospif((float)i * (1.0f / 128.0f), &s, &c);
        tab4[i] = make_float4(c, c, s, s);
    }
    {
        const float* srcR = g_Tre + (size_t)((b * 16 + kx) * 256) * 32 + ch * 16;
        const float* srcI = g_Tim + (size_t)((b * 16 + kx) * 256) * 32 + ch * 16;
        for (int i = t; i < 4096; i += 128) {
            const int h = i >> 4, cl = i & 15;
            sTre[i] = srcR[h * 32 + cl];
            sTim[i] = srcI[h * 32 + cl];
        }
    }
    __syncthreads();

    const int p = t >> 3;
    const int cp2 = (t & 7) * 2;
    const int incb = (p + 240) & 255;   // f = p - 16 mod 256
    const u64 neg1 = pack2(-1.0f, -1.0f);
    u64 aRe = 0, aIm = 0, bRe = 0, bIm = 0;
    int ia = 0, ib = 0;
#pragma unroll 2
    for (int h = 0; h < 256; h++) {
        const u64 Tr = *(const u64*)&sTre[h * 16 + cp2];
        const u64 Ti = *(const u64*)&sTim[h * 16 + cp2];
        const u64 Trn = fmul2(Tr, neg1);
        const ulonglong2 ta = *(const ulonglong2*)&tab4[ia]; ia = (ia + p) & 255;
        const ulonglong2 tb = *(const ulonglong2*)&tab4[ib]; ib = (ib + incb) & 255;
        // X = T * e^{-i th}: re += Tr c + Ti s ; im += Ti c - Tr s
        aRe = ffma2(Tr, ta.x, aRe); aRe = ffma2(Ti, ta.y, aRe);
        aIm = ffma2(Ti, ta.x, aIm); aIm = ffma2(Trn, ta.y, aIm);
        bRe = ffma2(Tr, tb.x, bRe); bRe = ffma2(Ti, tb.y, bRe);
        bIm = ffma2(Ti, tb.x, bIm); bIm = ffma2(Trn, tb.y, bIm);
    }
    const int c = ch * 16 + cp2;
    const size_t ixa = (size_t)(p * 16 + kx) * 256 + b * 32 + c;
    const size_t ixb = (size_t)((p + 16) * 16 + kx) * 256 + b * 32 + c;
    *(float2*)&g_Xre[ixa] = unpack2(aRe);
    *(float2*)&g_Xim[ixa] = unpack2(aIm);
    *(float2*)&g_Xre[ixb] = unpack2(bRe);
    *(float2*)&g_Xim[ixb] = unpack2(bIm);
}

// ---------------------------------------------------------------------------
// K3: channel mixing. Y[b,co,p,kx] = sum_ci X[p,kx,b,ci] * W[blk,ci,co,m1,kx]
// grid (16 kx, 32 p), 256 threads.
// ---------------------------------------------------------------------------
__global__ __launch_bounds__(256) void k3_mix(const float* __restrict__ wr,
                                              const float* __restrict__ wi) {
    __shared__ float sXr[256], sXi[256];
    __shared__ float swr[1024], swi[1024];
    const int t = threadIdx.x;
    const int kx = blockIdx.x, p = blockIdx.y;

    sXr[t] = g_Xre[(size_t)(p * 16 + kx) * 256 + t];
    sXi[t] = g_Xim[(size_t)(p * 16 + kx) * 256 + t];
    const int blk = p >> 4, m1 = p & 15;
    const float* wrb = wr + blk * 262144 + m1 * 16 + kx;
    const float* wib = wi + blk * 262144 + m1 * 16 + kx;
    for (int i = t; i < 1024; i += 256) {
        const int ci = i >> 5, co = i & 31;
        swr[i] = wrb[ci * 8192 + co * 256];
        swi[i] = wib[ci * 8192 + co * 256];
    }
    __syncthreads();

    const int b = t >> 5, co = t & 31;
    float accR = 0.f, accI = 0.f;
#pragma unroll
    for (int ci = 0; ci < 32; ci++) {
        const float Xr = sXr[b * 32 + ci], Xi = sXi[b * 32 + ci];
        const float Wr = swr[ci * 32 + co], Wi = swi[ci * 32 + co];
        accR += Xr * Wr - Xi * Wi;
        accI += Xr * Wi + Xi * Wr;
    }
    const size_t g = ((size_t)(b * 32 + co) * 32 + p) * 16 + kx;
    g_Yre[g] = accR;
    g_Yim[g] = accI;
}

// ---------------------------------------------------------------------------
// K4: inverse DFT over h, f32x2 over co pairs, split kx for occupancy.
// grid (4 hc, 8 = cc*kxc, 8 b) = 256 blocks, 256 threads (64 h x 4 co-pairs).
// ---------------------------------------------------------------------------
__global__ __launch_bounds__(256) void k4_idft_h() {
    __shared__ __align__(16) float sYr[2048], sYi[2048];  // [p][kxl][col]
    __shared__ __align__(16) float4 tab4[256];            // (c, c, s, s)
    const int t = threadIdx.x;
    const int hc = blockIdx.x;
    const int cc = blockIdx.y & 3, kxc = blockIdx.y >> 2;
    const int b = blockIdx.z;

    {
        float s, c; sincospif((float)t * (1.0f / 128.0f), &s, &c);
        tab4[t] = make_float4(c, c, s, s);
    }
    for (int i = t; i < 2048; i += 256) {
        const int kxl = i & 7, col = (i >> 3) & 7, p = i >> 6;
        const int co = cc * 8 + col, kx = kxc * 8 + kxl;
        const size_t g = ((size_t)(b * 32 + co) * 32 + p) * 16 + kx;
        sYr[(p * 8 + kxl) * 8 + col] = g_Yre[g];
        sYi[(p * 8 + kxl) * 8 + col] = g_Yim[g];
    }
    __syncthreads();

    const int hl = t >> 2, cp2 = (t & 3) * 2;
    const int h = hc * 64 + hl;
    u64 aRe[8], aIm[8];
#pragma unroll
    for (int k = 0; k < 8; k++) { aRe[k] = 0; aIm[k] = 0; }
    const u64 neg1 = pack2(-1.0f, -1.0f);

    int m = 0;                                 // p = 0..15: f = p
#pragma unroll 1
    for (int p = 0; p < 16; p++) {
        const ulonglong2 tv = *(const ulonglong2*)&tab4[m]; m = (m + h) & 255;
        const u64 tc = tv.x, ts = tv.y, tsn = fmul2(ts, neg1);
#pragma unroll
        for (int k = 0; k < 8; k++) {
            const u64 Yr = *(const u64*)&sYr[(p * 8 + k) * 8 + cp2];
            const u64 Yi = *(const u64*)&sYi[(p * 8 + k) * 8 + cp2];
            aRe[k] = ffma2(Yr, tc, aRe[k]); aRe[k] = ffma2(Yi, tsn, aRe[k]);
            aIm[k] = ffma2(Yr, ts, aIm[k]); aIm[k] = ffma2(Yi, tc,  aIm[k]);
        }
    }
    m = (-16 * h) & 255;                       // p = 16..31: f = p - 32
#pragma unroll 1
    for (int p = 16; p < 32; p++) {
        const ulonglong2 tv = *(const ulonglong2*)&tab4[m]; m = (m + h) & 255;
        const u64 tc = tv.x, ts = tv.y, tsn = fmul2(ts, neg1);
#pragma unroll
        for (int k = 0; k < 8; k++) {
            const u64 Yr = *(const u64*)&sYr[(p * 8 + k) * 8 + cp2];
            const u64 Yi = *(const u64*)&sYi[(p * 8 + k) * 8 + cp2];
            aRe[k] = ffma2(Yr, tc, aRe[k]); aRe[k] = ffma2(Yi, tsn, aRe[k]);
            aIm[k] = ffma2(Yr, ts, aIm[k]); aIm[k] = ffma2(Yi, tc,  aIm[k]);
        }
    }

#pragma unroll
    for (int k = 0; k < 8; k++) {
        const int kx = kxc * 8 + k;
        const float s = (kx == 0 ? 1.0f : 2.0f) * (1.0f / 65536.0f);
        float2 r = unpack2(aRe[k]); r.x *= s; r.y *= s;
        float2 im = unpack2(aIm[k]); im.x *= s; im.y *= s;
        const size_t g = ((size_t)(b * 256 + h) * 16 + kx) * 32 + cc * 8 + cp2;
        *(float2*)&g_Gre[g] = r;
        *(float2*)&g_Gim[g] = im;
    }
}

// ---------------------------------------------------------------------------
// K5: inverse DFT over w, f32x2 over the (w, w+128) pair:
// tw(w+128, k) = tw(w, k) * (-1)^k, baked into the table second lane.
// grid 2048 (b*256+h), 256 threads.
// ---------------------------------------------------------------------------
__global__ __launch_bounds__(256) void k5_idft_w(float* __restrict__ out) {
    __shared__ __align__(16) float4 stw4[128 * 16];  // (c, sg c, -s, -sg s) 32 KB
    __shared__ __align__(16) float2 tab[256];
    const int t = threadIdx.x;
    const int blk = blockIdx.x;   // b*256 + h

    {
        float s, c; sincospif((float)t * (1.0f / 128.0f), &s, &c);
        tab[t] = make_float2(c, s);
    }
    __syncthreads();
    if (t < 128) {
        const int w = t;
        int m = 0;
#pragma unroll
        for (int k = 0; k < 16; k++) {
            const float c = tab[m].x, s = tab[m].y;
            m = (m + w) & 255;
            const float sg = (k & 1) ? -1.0f : 1.0f;
            stw4[w * 16 + k] = make_float4(c, sg * c, -s, -sg * s);
        }
    }
    const int co = t & 31, ws = t >> 5;
    u64 grp[16], gip[16];
    {
        const float* Gr = g_Gre + (size_t)blk * 512 + co;
        const float* Gi = g_Gim + (size_t)blk * 512 + co;
#pragma unroll
        for (int k = 0; k < 16; k++) {
            const float r = Gr[k * 32], ii = Gi[k * 32];
            grp[k] = pack2(r, r);
            gip[k] = pack2(ii, ii);
        }
    }
    __syncthreads();

    float* outp = out + (size_t)blk * 8192 + co;
#pragma unroll 1
    for (int j = 0; j < 16; j++) {
        const int w = j * 8 + ws;
        const ulonglong2* tw = (const ulonglong2*)&stw4[w * 16];
        u64 acc = 0;
#pragma unroll
        for (int k = 0; k < 16; k++) {
            const ulonglong2 v = tw[k];
            acc = ffma2(grp[k], v.x, acc);
            acc = ffma2(gip[k], v.y, acc);
        }
        const float2 r = unpack2(acc);
        outp[(size_t)w * 32] = r.x;
        outp[(size_t)(w + 128) * 32] = r.y;
    }
}

// ---------------------------------------------------------------------------
extern "C" void kernel_launch(void* const* d_in, const int* in_sizes, int n_in,
                              void* d_out, int out_size) {
    (void)n_in; (void)out_size; (void)in_sizes;
    const float* x  = (const float*)d_in[0];
    const float* wr = (const float*)d_in[1];
    const float* wi = (const float*)d_in[2];
    float* out = (float*)d_out;

    k1_dft_w<<<2048, 64>>>(x);
    k2_dft_h<<<dim3(16, 2, 8), 128>>>();
    k3_mix<<<dim3(16, 32), 256>>>(wr, wi);
    k4_idft_h<<<dim3(4, 8, 8), 256>>>();
    k5_idft_w<<<2048, 256>>>(out);
}

// round 4
// speedup vs baseline: 1.3179x; 1.3179x over previous
#include <cuda_runtime.h>
#include <math.h>

// FNO spectral conv: truncated separable DFTs + mirror symmetries.
// B=8, H=W=256, CIN=COUT=32, M1=M2=16.
typedef unsigned long long u64;
typedef ulonglong2 u64x2;

// Precomputed tables / transposed weights / scratch (device globals).
__device__ __align__(16) float4 g_tab4[256];    // (cos, cos, sin, sin)
__device__ __align__(8)  float2 g_tab2[256];    // (cos, sin)
__device__ __align__(16) float  g_wtr[524288];  // [blk][m1][kx][ci][co]
__device__ __align__(16) float  g_wti[524288];
__device__ __align__(16) float  g_Tre[1048576]; // [b][kx][h][c]
__device__ __align__(16) float  g_Tim[1048576];
__device__ __align__(16) float  g_Xre[131072];  // [p*16+kx][b*32+c]
__device__ __align__(16) float  g_Xim[131072];
__device__ __align__(16) float  g_Yre[131072];  // [p*16+kx][b*32+co]
__device__ __align__(16) float  g_Yim[131072];
__device__ __align__(16) float  g_Gre[1048576]; // [b][h][kx][co]
__device__ __align__(16) float  g_Gim[1048576];

__device__ __forceinline__ u64 pack2(float lo, float hi) {
    u64 r; asm("mov.b64 %0,{%1,%2};" : "=l"(r) : "f"(lo), "f"(hi)); return r;
}
__device__ __forceinline__ float2 unpack2(u64 v) {
    float2 f; asm("mov.b64 {%0,%1},%2;" : "=f"(f.x), "=f"(f.y) : "l"(v)); return f;
}
__device__ __forceinline__ u64 ffma2(u64 a, u64 b, u64 c) {
    u64 d; asm("fma.rn.f32x2 %0,%1,%2,%3;" : "=l"(d) : "l"(a), "l"(b), "l"(c)); return d;
}
__device__ __forceinline__ u64 fmul2(u64 a, u64 b) {
    u64 d; asm("mul.rn.f32x2 %0,%1,%2;" : "=l"(d) : "l"(a), "l"(b)); return d;
}

// ---------------------------------------------------------------------------
// K0: build twiddle tables + transpose weights to [blk][m1][kx][ci][co].
// grid 2048 x 256 threads (one element each; reads coalesced).
// ---------------------------------------------------------------------------
__global__ __launch_bounds__(256) void k0_init(const float* __restrict__ wr,
                                               const float* __restrict__ wi) {
    const int t = threadIdx.x, bid = blockIdx.x;
    if (bid == 0) {
        float s, c; sincospif((float)t * (1.0f / 128.0f), &s, &c);
        g_tab4[t] = make_float4(c, c, s, s);
        g_tab2[t] = make_float2(c, s);
    }
    const int lin = bid * 256 + t;   // w layout: [blk][ci][co][m1][kx]
    const int kx = lin & 15, m1 = (lin >> 4) & 15, co = (lin >> 8) & 31;
    const int ci = (lin >> 13) & 31, blk = lin >> 18;
    const int dst = ((blk * 16 + m1) * 16 + kx) * 1024 + ci * 32 + co;
    g_wtr[dst] = wr[lin];
    g_wti[dst] = wi[lin];
}

// ---------------------------------------------------------------------------
// K1: forward DFT over w with real-input mirror symmetry.
// T[kx] = x0 + (-1)^kx x128 + sum_{w=1..127} e[w] cos - i o[w] sin.
// grid 2048 (b*256+h), 128 threads: thread = kx(16) x cquad(8 -> 4 channels).
// ---------------------------------------------------------------------------
__global__ __launch_bounds__(128) void k1_dft_w(const float* __restrict__ x) {
    __shared__ __align__(16) float4 se[128 * 8], so[128 * 8];
    __shared__ __align__(16) float4 stab[256];
    __shared__ __align__(16) float4 sx0[8], sx128[8];
    const int t = threadIdx.x;
    const int blk = blockIdx.x;                       // b*256 + h
    const float4* xb = (const float4*)(x + (size_t)blk * 8192);

    for (int i = t; i < 256; i += 128) stab[i] = g_tab4[i];
    for (int i = t; i < 1016; i += 128) {
        const int w = 1 + (i >> 3), cq = i & 7;
        const float4 a = xb[w * 8 + cq];
        const float4 bb = xb[(256 - w) * 8 + cq];
        se[w * 8 + cq] = make_float4(a.x + bb.x, a.y + bb.y, a.z + bb.z, a.w + bb.w);
        so[w * 8 + cq] = make_float4(a.x - bb.x, a.y - bb.y, a.z - bb.z, a.w - bb.w);
    }
    if (t < 8) { sx0[t] = xb[t]; sx128[t] = xb[1024 + t]; }
    __syncthreads();

    const int kx = t >> 3, cq = t & 7;
    const float sg = (kx & 1) ? -1.0f : 1.0f;
    const u64 sg2 = pack2(sg, sg);
    const u64x2 e0 = *(const u64x2*)&sx0[cq];
    const u64x2 e1 = *(const u64x2*)&sx128[cq];
    u64 re0 = ffma2(e1.x, sg2, e0.x);
    u64 re1 = ffma2(e1.y, sg2, e0.y);
    u64 im0 = 0, im1 = 0;
    int m = kx;
#pragma unroll 4
    for (int w = 1; w < 128; w++) {
        const u64x2 ev = *(const u64x2*)&se[w * 8 + cq];
        const u64x2 ov = *(const u64x2*)&so[w * 8 + cq];
        const u64x2 tv = *(const u64x2*)&stab[m];
        m = (m + kx) & 255;
        re0 = ffma2(ev.x, tv.x, re0); re1 = ffma2(ev.y, tv.x, re1);
        im0 = ffma2(ov.x, tv.y, im0); im1 = ffma2(ov.y, tv.y, im1);
    }
    const int b = blk >> 8, h = blk & 255;
    const size_t o4 = ((size_t)((b * 16 + kx) * 256 + h)) * 8 + cq;
    const float2 r0 = unpack2(re0), r1 = unpack2(re1);
    ((float4*)g_Tre)[o4] = make_float4(r0.x, r0.y, r1.x, r1.y);
    const u64 n1 = pack2(-1.0f, -1.0f);
    const float2 i0 = unpack2(fmul2(im0, n1)), i1 = unpack2(fmul2(im1, n1));
    ((float4*)g_Tim)[o4] = make_float4(i0.x, i0.y, i1.x, i1.y);
}

// ---------------------------------------------------------------------------
// K2: forward DFT over h (32 kept modes) with complex mirror symmetry.
// X = T0 + (-1)^f T128 + sum_{h=1..127} [E_r c + O_i s] + i [E_i c - O_r s].
// Frequencies: f = p for p<16 (low block), f = p+224 (= p-32 mod 256) for the
// high block rows p = 16..31 (reference rows H-16..H-1).
// grid (16 kx, 2 ch, 8 b), 256 threads: thread = p(32) x cpair(8).
// ---------------------------------------------------------------------------
__global__ __launch_bounds__(256) void k2_dft_h() {
    __shared__ __align__(16) float4 sA[128 * 8];   // {Er0,Er1,Oi0,Oi1}
    __shared__ __align__(16) float4 sB[128 * 8];   // {Ei0,Ei1,-Or0,-Or1}
    __shared__ __align__(16) float4 stab[256];
    __shared__ __align__(16) float4 sT0[8], sT128[8];
    const int t = threadIdx.x;
    const int kx = blockIdx.x, ch = blockIdx.y, b = blockIdx.z;
    const float* srcR = g_Tre + ((size_t)(b * 16 + kx) * 256) * 32 + ch * 16;
    const float* srcI = g_Tim + ((size_t)(b * 16 + kx) * 256) * 32 + ch * 16;

    stab[t] = g_tab4[t];
    for (int i = t; i < 1016; i += 256) {
        const int h = 1 + (i >> 3), cp = i & 7;
        const float2 ar = *(const float2*)&srcR[h * 32 + cp * 2];
        const float2 br = *(const float2*)&srcR[(256 - h) * 32 + cp * 2];
        const float2 ai = *(const float2*)&srcI[h * 32 + cp * 2];
        const float2 bi = *(const float2*)&srcI[(256 - h) * 32 + cp * 2];
        sA[(h << 3) + cp] = make_float4(ar.x + br.x, ar.y + br.y, ai.x - bi.x, ai.y - bi.y);
        sB[(h << 3) + cp] = make_float4(ai.x + bi.x, ai.y + bi.y, br.x - ar.x, br.y - ar.y);
    }
    if (t < 8) {
        sT0[t]   = make_float4(srcR[t * 2], srcR[t * 2 + 1], srcI[t * 2], srcI[t * 2 + 1]);
        sT128[t] = make_float4(srcR[4096 + t * 2], srcR[4096 + t * 2 + 1],
                               srcI[4096 + t * 2], srcI[4096 + t * 2 + 1]);
    }
    __syncthreads();

    const int p = t >> 3, cp = t & 7;
    const int f = (p < 16) ? p : (p + 224);           // FIX: high block f = p-32 mod 256
    const float sg = (p & 1) ? -1.0f : 1.0f;          // parity of f == parity of p
    const u64 sg2 = pack2(sg, sg);
    const u64x2 t0 = *(const u64x2*)&sT0[cp];
    const u64x2 t1 = *(const u64x2*)&sT128[cp];
    u64 aRe = ffma2(t1.x, sg2, t0.x);
    u64 aIm = ffma2(t1.y, sg2, t0.y);
    int m = f & 255;
#pragma unroll 4
    for (int h = 1; h < 128; h++) {
        const u64x2 A  = *(const u64x2*)&sA[(h << 3) + cp];
        const u64x2 Bv = *(const u64x2*)&sB[(h << 3) + cp];
        const u64x2 tv = *(const u64x2*)&stab[m];
        m = (m + f) & 255;
        aRe = ffma2(A.x, tv.x, aRe);  aRe = ffma2(A.y, tv.y, aRe);
        aIm = ffma2(Bv.x, tv.x, aIm); aIm = ffma2(Bv.y, tv.y, aIm);
    }
    const int c = ch * 16 + cp * 2;
    const size_t ix = (size_t)(p * 16 + kx) * 256 + b * 32 + c;
    *(float2*)&g_Xre[ix] = unpack2(aRe);
    *(float2*)&g_Xim[ix] = unpack2(aIm);
}

// ---------------------------------------------------------------------------
// K3: channel mixing with coalesced (transposed) weights.
// grid (16 kx, 32 p), 256 threads (one (b,co) each).
// ---------------------------------------------------------------------------
__global__ __launch_bounds__(256) void k3_mix() {
    __shared__ float sXr[256], sXi[256];
    __shared__ float swr[1024], swi[1024];
    const int t = threadIdx.x;
    const int kx = blockIdx.x, p = blockIdx.y;

    sXr[t] = g_Xre[(size_t)(p * 16 + kx) * 256 + t];
    sXi[t] = g_Xim[(size_t)(p * 16 + kx) * 256 + t];
    const int blk = p >> 4, m1 = p & 15;
    const int base = ((blk * 16 + m1) * 16 + kx) * 1024;
    for (int i = t; i < 1024; i += 256) {
        swr[i] = g_wtr[base + i];
        swi[i] = g_wti[base + i];
    }
    __syncthreads();

    const int b = t >> 5, co = t & 31;
    float accR = 0.f, accI = 0.f;
#pragma unroll
    for (int ci = 0; ci < 32; ci++) {
        const float Xr = sXr[b * 32 + ci], Xi = sXi[b * 32 + ci];
        const float Wr = swr[ci * 32 + co], Wi = swi[ci * 32 + co];
        accR += Xr * Wr - Xi * Wi;
        accI += Xr * Wi + Xi * Wr;
    }
    g_Yre[(size_t)(p * 16 + kx) * 256 + t] = accR;
    g_Yim[(size_t)(p * 16 + kx) * 256 + t] = accI;
}

// ---------------------------------------------------------------------------
// K4: inverse DFT over h. grid (8 hc, 8 = kxc4*cc2, 8 b) = 512 blocks,
// 256 threads: thread = hl(32) x copair(8); 4 kx per thread.
// ---------------------------------------------------------------------------
__global__ __launch_bounds__(256) void k4_idft_h() {
    __shared__ __align__(16) float4 sYA[1024];   // [(p*4+kxl)*8+cp] {Yr0,Yr1,Yi0,Yi1}
    __shared__ __align__(8)  float2 sYN[1024];   // {-Yi0,-Yi1}
    __shared__ __align__(16) float4 stab[256];
    const int t = threadIdx.x;
    const int hc = blockIdx.x;
    const int kxc = blockIdx.y >> 1, cc = blockIdx.y & 1;
    const int b = blockIdx.z;
    const int kx0 = kxc * 4;

    stab[t] = g_tab4[t];
    for (int i = t; i < 1024; i += 256) {
        const int p = i >> 5, kxl = (i >> 3) & 3, cp = i & 7;
        const size_t src = (size_t)(p * 16 + kx0 + kxl) * 256 + b * 32 + cc * 16 + cp * 2;
        const float2 yr = *(const float2*)&g_Yre[src];
        const float2 yi = *(const float2*)&g_Yim[src];
        sYA[i] = make_float4(yr.x, yr.y, yi.x, yi.y);
        sYN[i] = make_float2(-yi.x, -yi.y);
    }
    __syncthreads();

    const int hl = t >> 3, cp = t & 7;
    const int h = hc * 32 + hl;
    u64 Re[4], Im[4];
#pragma unroll
    for (int k = 0; k < 4; k++) { Re[k] = 0; Im[k] = 0; }

    int m = 0;                                   // p=0..15: f = p
#pragma unroll 1
    for (int p = 0; p < 16; p++) {
        const u64x2 tv = *(const u64x2*)&stab[m]; m = (m + h) & 255;
#pragma unroll
        for (int k = 0; k < 4; k++) {
            const u64x2 A = *(const u64x2*)&sYA[(p * 4 + k) * 8 + cp];
            const u64   N = *(const u64*)&sYN[(p * 4 + k) * 8 + cp];
            Re[k] = ffma2(A.x, tv.x, Re[k]); Re[k] = ffma2(N,   tv.y, Re[k]);
            Im[k] = ffma2(A.x, tv.y, Im[k]); Im[k] = ffma2(A.y, tv.x, Im[k]);
        }
    }
    m = (4096 - 16 * h) & 255;                   // p=16..31: f = p-32
#pragma unroll 1
    for (int p = 16; p < 32; p++) {
        const u64x2 tv = *(const u64x2*)&stab[m]; m = (m + h) & 255;
#pragma unroll
        for (int k = 0; k < 4; k++) {
            const u64x2 A = *(const u64x2*)&sYA[(p * 4 + k) * 8 + cp];
            const u64   N = *(const u64*)&sYN[(p * 4 + k) * 8 + cp];
            Re[k] = ffma2(A.x, tv.x, Re[k]); Re[k] = ffma2(N,   tv.y, Re[k]);
            Im[k] = ffma2(A.x, tv.y, Im[k]); Im[k] = ffma2(A.y, tv.x, Im[k]);
        }
    }

#pragma unroll
    for (int k = 0; k < 4; k++) {
        const int kx = kx0 + k;
        const float sc = (kx == 0 ? 1.0f : 2.0f) * (1.0f / 65536.0f);
        const u64 scl = pack2(sc, sc);
        const size_t dst = ((size_t)(b * 256 + h) * 16 + kx) * 32 + cc * 16 + cp * 2;
        *(float2*)&g_Gre[dst] = unpack2(fmul2(Re[k], scl));
        *(float2*)&g_Gim[dst] = unpack2(fmul2(Im[k], scl));
    }
}

// ---------------------------------------------------------------------------
// K5: inverse DFT over w, mirror quad: one (C,S) pair -> 4 outputs
// {w, w+128, 256-w, 128-w}. grid 2048 (b*256+h), 256 threads = co(32) x wg(8).
// ---------------------------------------------------------------------------
__device__ __forceinline__ void k5_body(const float4* stw, const u64* Gr, const u64* Gi,
                                        float* ob, int w, int co) {
    u64 C = 0, S = 0;
    const u64x2* tw = (const u64x2*)&stw[w * 16];
#pragma unroll
    for (int k = 0; k < 16; k++) {
        const u64x2 v = tw[k];
        C = ffma2(Gr[k], v.x, C);
        S = ffma2(Gi[k], v.y, S);
    }
    const float2 c2 = unpack2(C), s2 = unpack2(S);
    ob[w * 32 + co]                   = c2.x - s2.x;
    ob[(w + 128) * 32 + co]           = c2.y - s2.y;
    ob[(((256 - w) & 255)) * 32 + co] = c2.x + s2.x;
    ob[(128 - w) * 32 + co]           = c2.y + s2.y;
}

__global__ __launch_bounds__(256) void k5_idft_w(float* __restrict__ out) {
    __shared__ __align__(16) float4 stw[65 * 16];   // [w][k] (c, sg*c, s, sg*s)
    const int t = threadIdx.x;
    const int blk = blockIdx.x;                     // b*256 + h

    for (int i = t; i < 1040; i += 256) {
        const int w = i >> 4, k = i & 15;
        const float2 cs = g_tab2[(k * w) & 255];
        const float sgn = (k & 1) ? -1.0f : 1.0f;
        stw[i] = make_float4(cs.x, sgn * cs.x, cs.y, sgn * cs.y);
    }
    const int co = t & 31, wg = t >> 5;
    u64 Gr[16], Gi[16];
    {
        const float* pr = g_Gre + (size_t)blk * 512 + co;
        const float* pi = g_Gim + (size_t)blk * 512 + co;
#pragma unroll
        for (int k = 0; k < 16; k++) {
            const float r = pr[k * 32]; Gr[k] = pack2(r, r);
            const float u = pi[k * 32]; Gi[k] = pack2(u, u);
        }
    }
    __syncthreads();

    float* ob = out + (size_t)blk * 8192;
#pragma unroll 1
    for (int j = 0; j < 8; j++) k5_body(stw, Gr, Gi, ob, wg + 8 * j, co);
    if (wg == 0) k5_body(stw, Gr, Gi, ob, 64, co);
}

// ---------------------------------------------------------------------------
extern "C" void kernel_launch(void* const* d_in, const int* in_sizes, int n_in,
                              void* d_out, int out_size) {
    (void)n_in; (void)out_size; (void)in_sizes;
    const float* x  = (const float*)d_in[0];
    const float* wr = (const float*)d_in[1];
    const float* wi = (const float*)d_in[2];
    float* out = (float*)d_out;

    k0_init<<<2048, 256>>>(wr, wi);
    k1_dft_w<<<2048, 128>>>(x);
    k2_dft_h<<<dim3(16, 2, 8), 256>>>();
    k3_mix<<<dim3(16, 32), 256>>>();
    k4_idft_h<<<dim3(8, 8, 8), 256>>>();
    k5_idft_w<<<2048, 256>>>(out);
}